// round 2
// baseline (speedup 1.0000x reference)
#include <cuda_runtime.h>

#define BB 8
#define CC 14
#define HH 512
#define WW 512
#define PP (HH * WW)
#define KK 13            // classes 1..13
#define NBK (BB * KK)    // 104
#define GRID_BLOCKS ((BB * PP / 4) / 256)   // 2048

// Global scratch accumulators. __device__ globals are zero-initialized at
// module load; the last block resets them after consuming, so every
// invocation (correctness run + each graph replay) starts from zeros.
__device__ float        g_kl[NBK];
__device__ unsigned int g_n[NBK];
__device__ unsigned int g_flag[NBK];
__device__ unsigned int g_count;

__global__ __launch_bounds__(256) void bkd_fused_kernel(
    const float* __restrict__ S,
    const float* __restrict__ T,
    const int*   __restrict__ gt,
    float*       __restrict__ out)
{
    __shared__ float        s_kl[KK];
    __shared__ unsigned int s_n[KK];
    __shared__ unsigned int s_flag[KK];
    __shared__ unsigned int s_isLast;
    if (threadIdx.x < KK) {
        s_kl[threadIdx.x]   = 0.0f;
        s_n[threadIdx.x]    = 0u;
        s_flag[threadIdx.x] = 0u;
    }
    __syncthreads();

    const int tid = blockIdx.x * blockDim.x + threadIdx.x;
    const long long p0 = (long long)tid * 4;       // 4 pixels per thread
    const int b  = (int)(p0 / PP);                 // one b per block (P % 1024 == 0)
    const int hw = (int)(p0 % PP);
    const int h  = hw >> 9;                        // /512
    const int w  = hw & 511;

    // ---- boundary detection from gt labels (4-connectivity, zero border) ----
    const int* gtb = gt + (size_t)b * PP;
    int4 gc = *(const int4*)(gtb + hw);
    int4 gu = (h > 0)      ? *(const int4*)(gtb + hw - WW) : make_int4(-1, -1, -1, -1);
    int4 gd = (h < HH - 1) ? *(const int4*)(gtb + hw + WW) : make_int4(-1, -1, -1, -1);
    int gl = (w > 0)       ? gtb[hw - 1] : -1;     // left neighbor of lane 0
    int gr = (w + 4 < WW)  ? gtb[hw + 4] : -1;     // right neighbor of lane 3

    int gcv[4] = {gc.x, gc.y, gc.z, gc.w};
    int guv[4] = {gu.x, gu.y, gu.z, gu.w};
    int gdv[4] = {gd.x, gd.y, gd.z, gd.w};

    bool bnd[4];
#pragma unroll
    for (int j = 0; j < 4; j++) {
        int g     = gcv[j];
        int left  = (j == 0) ? gl : gcv[j - 1];
        int right = (j == 3) ? gr : gcv[j + 1];
        bnd[j] = (g >= 1) &&
                 (guv[j] != g || gdv[j] != g || left != g || right != g);
    }

    // ---- single-pass per-pixel softmax/KL accumulators ----
    // kl = A/Z_T + log(Z_S/Z_T), with
    //   Z_S = sum_c exp(xS_c), Z_T = sum_c exp(xT_c), A = sum_c exp(xT_c)*(xT_c - xS_c)
    float ZS[4] = {0.f, 0.f, 0.f, 0.f};
    float ZT[4] = {0.f, 0.f, 0.f, 0.f};
    float A [4] = {0.f, 0.f, 0.f, 0.f};

    const float* Sp = S + (size_t)b * CC * PP + hw;
    const float* Tp = T + (size_t)b * CC * PP + hw;

#pragma unroll
    for (int c = 0; c < CC; c++) {
        float4 xs = *(const float4*)(Sp + (size_t)c * PP);
        float4 xt = *(const float4*)(Tp + (size_t)c * PP);

        float es, et;
        es = __expf(xs.x); et = __expf(xt.x);
        ZS[0] += es; ZT[0] += et; A[0] = fmaf(et, xt.x - xs.x, A[0]);
        es = __expf(xs.y); et = __expf(xt.y);
        ZS[1] += es; ZT[1] += et; A[1] = fmaf(et, xt.y - xs.y, A[1]);
        es = __expf(xs.z); et = __expf(xt.z);
        ZS[2] += es; ZT[2] += et; A[2] = fmaf(et, xt.z - xs.z, A[2]);
        es = __expf(xs.w); et = __expf(xt.w);
        ZS[3] += es; ZT[3] += et; A[3] = fmaf(et, xt.w - xs.w, A[3]);
    }

    // ---- per-block shared accumulation into 13 class bins ----
#pragma unroll
    for (int j = 0; j < 4; j++) {
        if (bnd[j]) {
            float kl = A[j] / ZT[j] + __logf(ZS[j] / ZT[j]);
            int k = gcv[j] - 1;
            atomicAdd(&s_kl[k], kl);
            atomicAdd(&s_n[k], 1u);
            if (hw + j > 0) s_flag[k] = 1u;   // idempotent racing write
        }
    }
    __syncthreads();

    if (threadIdx.x < KK) {
        int k   = threadIdx.x;
        int idx = b * KK + k;
        if (s_n[k] > 0u) {
            atomicAdd(&g_kl[idx], s_kl[k]);
            atomicAdd(&g_n[idx],  s_n[k]);
        }
        if (s_flag[k]) atomicOr(&g_flag[idx], 1u);
    }

    // ---- last-block-done finalize (fused reduction + scratch reset) ----
    __threadfence();
    if (threadIdx.x == 0) {
        unsigned int v = atomicAdd(&g_count, 1u);
        s_isLast = (v == (unsigned int)(GRID_BLOCKS - 1)) ? 1u : 0u;
    }
    __syncthreads();

    if (s_isLast) {
        __shared__ float sred[256];
        int i = threadIdx.x;
        float t = 0.0f;
        unsigned int nval = 0u, fval = 0u;
        float klval = 0.0f;
        if (i < NBK) {
            klval = g_kl[i];
            nval  = g_n[i];
            fval  = g_flag[i];
            if (fval) {
                unsigned int n = (nval < 1u) ? 1u : nval;
                t = klval / (14.0f * (float)n);
            }
        }
        sred[i] = t;
        __syncthreads();
#pragma unroll
        for (int s = 128; s > 0; s >>= 1) {
            if (i < s) sred[i] += sred[i + s];
            __syncthreads();
        }
        if (i == 0) {
            out[0] = sred[0];       // LOSS_WEIGHT * TAU^2 == 1
            g_count = 0u;           // reset counter for next replay
        }
        // reset scratch for next graph replay
        if (i < NBK) {
            g_kl[i]   = 0.0f;
            g_n[i]    = 0u;
            g_flag[i] = 0u;
        }
    }
}

extern "C" void kernel_launch(void* const* d_in, const int* in_sizes, int n_in,
                              void* d_out, int out_size) {
    const float* S  = (const float*)d_in[0];
    const float* T  = (const float*)d_in[1];
    const int*   gt = (const int*)d_in[2];
    float* out = (float*)d_out;

    bkd_fused_kernel<<<GRID_BLOCKS, 256>>>(S, T, gt, out);
}

// round 3
// speedup vs baseline: 1.1250x; 1.1250x over previous
#include <cuda_runtime.h>

#define BB 8
#define CC 14
#define HH 512
#define WW 512
#define PP (HH * WW)          // 262144 = 2^18
#define KK 13                 // classes 1..13
#define NBK (BB * KK)         // 104
#define THREADS 256
#define GRID_BLOCKS ((BB * PP / 2) / THREADS)   // 4096

// Global scratch. Zero-initialized at module load; the last block resets
// them after consuming, so every invocation starts from zeros.
__device__ float        g_kl[NBK];
__device__ unsigned int g_n[NBK];
__device__ unsigned int g_flag[NBK];
__device__ unsigned int g_count;

__global__ void __launch_bounds__(THREADS, 7) bkd_fused_kernel(
    const float* __restrict__ S,
    const float* __restrict__ T,
    const int*   __restrict__ gt,
    float*       __restrict__ out)
{
    __shared__ float        s_kl[KK];
    __shared__ unsigned int s_n[KK];
    __shared__ unsigned int s_flag[KK];
    __shared__ unsigned int s_isLast;
    if (threadIdx.x < KK) {
        s_kl[threadIdx.x]   = 0.0f;
        s_n[threadIdx.x]    = 0u;
        s_flag[threadIdx.x] = 0u;
    }
    __syncthreads();

    const int tid = blockIdx.x * blockDim.x + threadIdx.x;
    const int p0  = tid << 1;                // 2 pixels per thread
    const int b   = p0 >> 18;                // / PP
    const int hw  = p0 & (PP - 1);
    const int h   = hw >> 9;                 // / 512
    const int w   = hw & 511;

    // ---- boundary detection (4-connectivity, zero border) ----
    const int* gtb = gt + (size_t)b * PP;
    int2 gc = *(const int2*)(gtb + hw);
    int2 gu = (h > 0)      ? *(const int2*)(gtb + hw - WW) : make_int2(-1, -1);
    int2 gd = (h < HH - 1) ? *(const int2*)(gtb + hw + WW) : make_int2(-1, -1);
    int gl = (w > 0)       ? gtb[hw - 1] : -1;
    int gr = (w + 2 < WW)  ? gtb[hw + 2] : -1;

    bool bnd0 = (gc.x >= 1) &&
                (gu.x != gc.x || gd.x != gc.x || gl   != gc.x || gc.y != gc.x);
    bool bnd1 = (gc.y >= 1) &&
                (gu.y != gc.y || gd.y != gc.y || gc.x != gc.y || gr   != gc.y);

    // ---- single-pass per-pixel softmax/KL accumulators ----
    // kl = A/Z_T + log(Z_S/Z_T)
    float ZS0 = 0.f, ZS1 = 0.f;
    float ZT0 = 0.f, ZT1 = 0.f;
    float A0  = 0.f, A1  = 0.f;

    const float* Sp = S + (size_t)b * CC * PP + hw;
    const float* Tp = T + (size_t)b * CC * PP + hw;

#pragma unroll
    for (int c = 0; c < CC; c++) {
        float2 xs = *(const float2*)(Sp + (size_t)c * PP);
        float2 xt = *(const float2*)(Tp + (size_t)c * PP);

        float es0 = __expf(xs.x), et0 = __expf(xt.x);
        float es1 = __expf(xs.y), et1 = __expf(xt.y);
        ZS0 += es0; ZT0 += et0; A0 = fmaf(et0, xt.x - xs.x, A0);
        ZS1 += es1; ZT1 += et1; A1 = fmaf(et1, xt.y - xs.y, A1);
    }

    // ---- per-block shared accumulation into 13 class bins ----
    if (bnd0) {
        float r  = __fdividef(1.0f, ZT0);
        float kl = A0 * r + __logf(ZS0 * r);
        int k = gc.x - 1;
        atomicAdd(&s_kl[k], kl);
        atomicAdd(&s_n[k], 1u);
        if (hw > 0) s_flag[k] = 1u;           // idempotent racing write
    }
    if (bnd1) {
        float r  = __fdividef(1.0f, ZT1);
        float kl = A1 * r + __logf(ZS1 * r);
        int k = gc.y - 1;
        atomicAdd(&s_kl[k], kl);
        atomicAdd(&s_n[k], 1u);
        s_flag[k] = 1u;                        // hw+1 > 0 always
    }
    __syncthreads();

    if (threadIdx.x < KK) {
        int k   = threadIdx.x;
        int idx = b * KK + k;
        if (s_n[k] > 0u) {
            atomicAdd(&g_kl[idx], s_kl[k]);
            atomicAdd(&g_n[idx],  s_n[k]);
        }
        if (s_flag[k]) atomicOr(&g_flag[idx], 1u);
    }

    // ---- last-block-done finalize (fused reduction + scratch reset) ----
    __threadfence();
    if (threadIdx.x == 0) {
        unsigned int v = atomicAdd(&g_count, 1u);
        s_isLast = (v == (unsigned int)(GRID_BLOCKS - 1)) ? 1u : 0u;
    }
    __syncthreads();

    if (s_isLast) {
        __shared__ float sred[256];
        int i = threadIdx.x;
        float t = 0.0f;
        if (i < NBK && g_flag[i]) {
            unsigned int n = g_n[i];
            if (n < 1u) n = 1u;
            t = g_kl[i] / (14.0f * (float)n);
        }
        sred[i] = t;
        __syncthreads();
#pragma unroll
        for (int s = 128; s > 0; s >>= 1) {
            if (i < s) sred[i] += sred[i + s];
            __syncthreads();
        }
        if (i == 0) {
            out[0] = sred[0];        // LOSS_WEIGHT * TAU^2 == 1
            g_count = 0u;            // reset for next replay
        }
        if (i < NBK) {
            g_kl[i]   = 0.0f;
            g_n[i]    = 0u;
            g_flag[i] = 0u;
        }
    }
}

extern "C" void kernel_launch(void* const* d_in, const int* in_sizes, int n_in,
                              void* d_out, int out_size) {
    const float* S  = (const float*)d_in[0];
    const float* T  = (const float*)d_in[1];
    const int*   gt = (const int*)d_in[2];
    float* out = (float*)d_out;

    bkd_fused_kernel<<<GRID_BLOCKS, THREADS>>>(S, T, gt, out);
}

// round 4
// speedup vs baseline: 1.2143x; 1.0794x over previous
#include <cuda_runtime.h>

#define BB 8
#define CC 14
#define HH 512
#define WW 512
#define PP (HH * WW)          // 262144 = 2^18
#define KK 13                 // classes 1..13
#define NBK (BB * KK)         // 104
#define THREADS 256
#define GRID_BLOCKS ((BB * PP / 2) / THREADS)   // 4096
#define DEPTH 4               // software-pipeline depth (channels prefetched)

// Global scratch. Zero-initialized at module load; the last block resets
// them after consuming, so every invocation starts from zeros.
__device__ float        g_kl[NBK];
__device__ unsigned int g_n[NBK];
__device__ unsigned int g_flag[NBK];
__device__ unsigned int g_count;

__global__ void __launch_bounds__(THREADS, 6) bkd_fused_kernel(
    const float* __restrict__ S,
    const float* __restrict__ T,
    const int*   __restrict__ gt,
    float*       __restrict__ out)
{
    __shared__ float        s_kl[KK];
    __shared__ unsigned int s_n[KK];
    __shared__ unsigned int s_flag[KK];
    __shared__ unsigned int s_isLast;
    if (threadIdx.x < KK) {
        s_kl[threadIdx.x]   = 0.0f;
        s_n[threadIdx.x]    = 0u;
        s_flag[threadIdx.x] = 0u;
    }
    __syncthreads();

    const int tid = blockIdx.x * blockDim.x + threadIdx.x;
    const int p0  = tid << 1;                // 2 pixels per thread
    const int b   = p0 >> 18;                // / PP
    const int hw  = p0 & (PP - 1);
    const int h   = hw >> 9;                 // / 512
    const int w   = hw & 511;

    const float* Sp = S + (size_t)b * CC * PP + hw;
    const float* Tp = T + (size_t)b * CC * PP + hw;

    // ---- prime the pipeline: issue first DEPTH channels of loads ----
    float2 bs[DEPTH], bt[DEPTH];
#pragma unroll
    for (int i = 0; i < DEPTH; i++) {
        bs[i] = __ldcs((const float2*)(Sp + (size_t)i * PP));
        bt[i] = __ldcs((const float2*)(Tp + (size_t)i * PP));
    }

    // ---- boundary detection (overlaps with in-flight S/T loads) ----
    const int* gtb = gt + (size_t)b * PP;
    int2 gc = *(const int2*)(gtb + hw);
    int2 gu = (h > 0)      ? *(const int2*)(gtb + hw - WW) : make_int2(-1, -1);
    int2 gd = (h < HH - 1) ? *(const int2*)(gtb + hw + WW) : make_int2(-1, -1);
    int gl = (w > 0)       ? gtb[hw - 1] : -1;
    int gr = (w + 2 < WW)  ? gtb[hw + 2] : -1;

    bool bnd0 = (gc.x >= 1) &&
                (gu.x != gc.x || gd.x != gc.x || gl   != gc.x || gc.y != gc.x);
    bool bnd1 = (gc.y >= 1) &&
                (gu.y != gc.y || gd.y != gc.y || gc.x != gc.y || gr   != gc.y);

    // ---- pipelined single-pass softmax/KL accumulation ----
    // kl = A/Z_T + log(Z_S/Z_T)
    float ZS0 = 0.f, ZS1 = 0.f;
    float ZT0 = 0.f, ZT1 = 0.f;
    float A0  = 0.f, A1  = 0.f;

#pragma unroll
    for (int c = 0; c < CC; c++) {
        const int slot = c % DEPTH;           // constant after unroll
        float2 xs = bs[slot];
        float2 xt = bt[slot];
        if (c + DEPTH < CC) {                 // issue next loads BEFORE compute
            bs[slot] = __ldcs((const float2*)(Sp + (size_t)(c + DEPTH) * PP));
            bt[slot] = __ldcs((const float2*)(Tp + (size_t)(c + DEPTH) * PP));
        }
        float es0 = __expf(xs.x), et0 = __expf(xt.x);
        float es1 = __expf(xs.y), et1 = __expf(xt.y);
        ZS0 += es0; ZT0 += et0; A0 = fmaf(et0, xt.x - xs.x, A0);
        ZS1 += es1; ZT1 += et1; A1 = fmaf(et1, xt.y - xs.y, A1);
    }

    // ---- per-block shared accumulation into 13 class bins ----
    if (bnd0) {
        float r  = __fdividef(1.0f, ZT0);
        float kl = A0 * r + __logf(ZS0 * r);
        int k = gc.x - 1;
        atomicAdd(&s_kl[k], kl);
        atomicAdd(&s_n[k], 1u);
        if (hw > 0) s_flag[k] = 1u;           // idempotent racing write
    }
    if (bnd1) {
        float r  = __fdividef(1.0f, ZT1);
        float kl = A1 * r + __logf(ZS1 * r);
        int k = gc.y - 1;
        atomicAdd(&s_kl[k], kl);
        atomicAdd(&s_n[k], 1u);
        s_flag[k] = 1u;                        // hw+1 > 0 always
    }
    __syncthreads();

    if (threadIdx.x < KK) {
        int k   = threadIdx.x;
        int idx = b * KK + k;
        if (s_n[k] > 0u) {
            atomicAdd(&g_kl[idx], s_kl[k]);
            atomicAdd(&g_n[idx],  s_n[k]);
        }
        if (s_flag[k]) atomicOr(&g_flag[idx], 1u);
    }

    // ---- last-block-done finalize (fused reduction + scratch reset) ----
    __threadfence();
    if (threadIdx.x == 0) {
        unsigned int v = atomicAdd(&g_count, 1u);
        s_isLast = (v == (unsigned int)(GRID_BLOCKS - 1)) ? 1u : 0u;
    }
    __syncthreads();

    if (s_isLast) {
        __shared__ float sred[256];
        int i = threadIdx.x;
        float t = 0.0f;
        if (i < NBK && g_flag[i]) {
            unsigned int n = g_n[i];
            if (n < 1u) n = 1u;
            t = g_kl[i] / (14.0f * (float)n);
        }
        sred[i] = t;
        __syncthreads();
#pragma unroll
        for (int s = 128; s > 0; s >>= 1) {
            if (i < s) sred[i] += sred[i + s];
            __syncthreads();
        }
        if (i == 0) {
            out[0] = sred[0];        // LOSS_WEIGHT * TAU^2 == 1
            g_count = 0u;            // reset for next replay
        }
        if (i < NBK) {
            g_kl[i]   = 0.0f;
            g_n[i]    = 0u;
            g_flag[i] = 0u;
        }
    }
}

extern "C" void kernel_launch(void* const* d_in, const int* in_sizes, int n_in,
                              void* d_out, int out_size) {
    const float* S  = (const float*)d_in[0];
    const float* T  = (const float*)d_in[1];
    const int*   gt = (const int*)d_in[2];
    float* out = (float*)d_out;

    bkd_fused_kernel<<<GRID_BLOCKS, THREADS>>>(S, T, gt, out);
}